// round 17
// baseline (speedup 1.0000x reference)
#include <cuda_runtime.h>
#include <cuda_fp16.h>
#include <cstdint>
#include <math.h>

// ---------------- problem constants ----------------
#define Gn   64
#define Cn   32
#define Ln   128
#define Dn   64
#define Hn   128
#define NG   512          // 4*H gate rows
#define NCLSn 10
#define BT   16           // sequences per CTA
#define NBATCH (Gn*Cn)    // 2048
#define NCTA (NBATCH/BT)  // 128
#define NTHR 512

__device__ float g_rep[NBATCH * Hn];

// ---------------- smem layout (bytes) ----------------
// W    : fp16 [512 r'][192 k], rows PERMUTED, 3 chunks of [512][64], 128B rows, SW128
// ACT0/1: fp16 [16 b][192 k], 3 chunks of [16][64], 128B rows, SW128
//   rows 0-7 owned by half A, rows 8-15 by half B (disjoint; halves drift in t)
#define SM_W     0                          // 196608
#define SM_ACT0  196608                     // 6144
#define SM_ACT1  (196608 + 6144)            // 6144
#define SM_TOTAL (SM_ACT1 + 6144)           // 208896

// ---------------- helpers ----------------
__device__ __forceinline__ uint32_t smem_u32(const void* p) {
    uint32_t a;
    asm("{ .reg .u64 t; cvta.to.shared.u64 t, %1; cvt.u32.u64 %0, t; }" : "=r"(a) : "l"(p));
    return a;
}
__device__ __forceinline__ uint32_t swz(uint32_t o) { return o ^ ((o >> 3) & 0x70); }
__device__ __forceinline__ uint32_t w_off(int n, int k) {
    return (uint32_t)((k >> 6) * 65536) + swz((uint32_t)(n * 128 + (k & 63) * 2));
}
__device__ __forceinline__ uint32_t b_off(int b, int k) {
    return (uint32_t)((k >> 6) * 2048) + swz((uint32_t)(b * 128 + (k & 63) * 2));
}
// W row permutation: gate-row n = g*128 + j  ->  r' = 32*(j>>3) + 8*g + (j&7)
__device__ __forceinline__ int wperm(int g, int j) {
    return 32 * (j >> 3) + 8 * g + (j & 7);
}

#define LDSM4(R, A)                                                            \
    asm volatile("ldmatrix.sync.aligned.m8n8.x4.shared.b16 {%0,%1,%2,%3}, [%4];" \
        : "=r"((R)[0]), "=r"((R)[1]), "=r"((R)[2]), "=r"((R)[3]) : "r"(A))
#define LDSM2(R, A)                                                            \
    asm volatile("ldmatrix.sync.aligned.m8n8.x2.shared.b16 {%0,%1}, [%2];"     \
        : "=r"((R)[0]), "=r"((R)[1]) : "r"(A))

// f16-accumulator MMA m16n8k16: C/D = 2 b32 regs
#define MMAH(C0, C1, A, B0, B1)                                                \
    asm volatile("mma.sync.aligned.m16n8k16.row.col.f16.f16.f16.f16 "          \
        "{%0,%1},{%2,%3,%4,%5},{%6,%7},{%0,%1};"                               \
        : "+r"(C0), "+r"(C1)                                                   \
        : "r"((A)[0]), "r"((A)[1]), "r"((A)[2]), "r"((A)[3]), "r"(B0), "r"(B1))

__device__ __forceinline__ __half2 u2h(uint32_t u) { return *reinterpret_cast<__half2*>(&u); }
__device__ __forceinline__ __half2 tanh_h2(__half2 x) {
    uint32_t u = *reinterpret_cast<uint32_t*>(&x), y;
    asm("tanh.approx.f16x2 %0, %1;" : "=r"(y) : "r"(u));
    return *reinterpret_cast<__half2*>(&y);
}
__device__ __forceinline__ __half2 sig_h2p(__half2 x) {
    const __half2 h05 = __float2half2_rn(0.5f);
    return __hfma2(tanh_h2(__hmul2(x, h05)), h05, h05);
}
__device__ __forceinline__ uint32_t packh2(float a, float b) {
    __half2 h = __floats2half2_rn(a, b);
    return *reinterpret_cast<uint32_t*>(&h);
}

// ---------------- LSTM kernel ----------------
extern "C" __global__ void __launch_bounds__(NTHR, 1)
lstm_kernel(const float* __restrict__ x,    // [2048][128][64]
            const float* __restrict__ Wih,  // [512][64]
            const float* __restrict__ Whh,  // [512][128]
            const float* __restrict__ bih,  // [512]
            const float* __restrict__ bhh)  // [512]
{
    extern __shared__ unsigned char smem[];
    const uint32_t sbase = smem_u32(smem);

    const int tid  = threadIdx.x;
    const int lane = tid & 31;
    const int wid  = tid >> 5;      // 0..15
    const int half = wid >> 3;      // 0 (b0-7) or 1 (b8-15)
    const int wl   = wid & 7;       // warp index within half
    const int b0   = blockIdx.x * BT;

    // ---- stage W (row-permuted) fp16, swizzled ----
    for (int i = tid; i < NG * Dn; i += NTHR) {
        int n = i >> 6, k = i & 63;
        int rp = wperm(n >> 7, n & 127);
        *(__half*)(smem + SM_W + w_off(rp, k)) = __float2half(Wih[i]);
    }
    for (int i = tid; i < NG * Hn; i += NTHR) {
        int n = i >> 7, k = 64 + (i & 127);
        int rp = wperm(n >> 7, n & 127);
        *(__half*)(smem + SM_W + w_off(rp, k)) = __float2half(Whh[i]);
    }
    // h_{-1} = 0 in ACT0 (all 16 b rows)
    for (int i = tid; i < BT * Hn; i += NTHR) {
        int b = i >> 7, jj = i & 127;
        *(__half*)(smem + SM_ACT0 + b_off(b, 64 + jj)) = __float2half(0.0f);
    }

    // ---- x staging: per-half, thread owns 2 (b,d) slots ----
    const int lt  = tid & 255;
    const int pd  = lt & 63;
    const int bx0 = half * 8 + (lt >> 6);        // half*8 + 0..3
    const int bx1 = bx0 + 4;
    const uint32_t xo0 = b_off(bx0, pd);
    const uint32_t xo1 = b_off(bx1, pd);
    const float* xbA = x + ((size_t)(b0 + bx0) * Ln) * Dn + pd;
    const float* xbB = x + ((size_t)(b0 + bx1) * Ln) * Dn + pd;
    float px0 = xbA[0], px1 = xbB[0];
    *(__half*)(smem + SM_ACT0 + xo0) = __float2half(px0);
    *(__half*)(smem + SM_ACT0 + xo1) = __float2half(px1);

    // ---- mma lane geometry ----
    // warp covers permuted rows 64*wl .. 64*wl+63 = 4 m16 tiles
    const int lr = lane & 7, lm = lane >> 3;
    const uint32_t a2 = (uint32_t)((lm >> 1) * 16);
    const uint32_t ax = (uint32_t)lr * 16;
    uint32_t aw[4];
    #pragma unroll
    for (int tl = 0; tl < 4; tl++)
        aw[tl] = sbase + SM_W + (uint32_t)(64 * wl + 16 * tl + (lm & 1) * 8 + lr) * 128;
    // B operand (ldmatrix.x2): lanes 0-15 give (b row, k-half)
    const uint32_t bk2 = (uint32_t)(((lane >> 3) & 1) * 16);
    const uint32_t bxm = (uint32_t)(lane & 7) * 16;
    const uint32_t brow = (uint32_t)(half * 8 + (lane & 7)) * 128;
    const uint32_t bw0 = sbase + SM_ACT0 + brow;
    const uint32_t bw1 = sbase + SM_ACT1 + brow;

    // ---- per-lane update geometry ----
    // jA = 16*wl + (lane>>2), jB = jA + 8; batches bA, bA+1 (half-local +8*half)
    const int jA = 16 * wl + (lane >> 2);
    const int jB = jA + 8;
    const int bA = half * 8 + 2 * (lane & 3);
    const uint32_t uBIa = packh2(bih[      jA] + bhh[      jA], bih[      jA] + bhh[      jA]);
    const uint32_t uBFa = packh2(bih[128 + jA] + bhh[128 + jA], bih[128 + jA] + bhh[128 + jA]);
    const uint32_t uBGa = packh2(bih[256 + jA] + bhh[256 + jA], bih[256 + jA] + bhh[256 + jA]);
    const uint32_t uBOa = packh2(bih[384 + jA] + bhh[384 + jA], bih[384 + jA] + bhh[384 + jA]);
    const uint32_t uBIb = packh2(bih[      jB] + bhh[      jB], bih[      jB] + bhh[      jB]);
    const uint32_t uBFb = packh2(bih[128 + jB] + bhh[128 + jB], bih[128 + jB] + bhh[128 + jB]);
    const uint32_t uBGb = packh2(bih[256 + jB] + bhh[256 + jB], bih[256 + jB] + bhh[256 + jB]);
    const uint32_t uBOb = packh2(bih[384 + jB] + bhh[384 + jB], bih[384 + jB] + bhh[384 + jB]);

    // h store offsets for (j, b): chunk((64+j)>>6)*2048 + b*128 + (((64+j)&63)*2 ^ ((b&7)*16))
    const uint32_t hcA = (uint32_t)((64 + jA) >> 6) * 2048u;
    const uint32_t hkA = (uint32_t)((64 + jA) & 63) * 2u;
    const uint32_t hcB = (uint32_t)((64 + jB) >> 6) * 2048u;
    const uint32_t hkB = (uint32_t)((64 + jB) & 63) * 2u;
    const uint32_t hoffA0 = hcA + (uint32_t)bA * 128u + (hkA ^ (((uint32_t)bA & 7) * 16u));
    const uint32_t hoffA1 = hcA + (uint32_t)(bA + 1) * 128u + (hkA ^ (((uint32_t)(bA + 1) & 7) * 16u));
    const uint32_t hoffB0 = hcB + (uint32_t)bA * 128u + (hkB ^ (((uint32_t)bA & 7) * 16u));
    const uint32_t hoffB1 = hcB + (uint32_t)(bA + 1) * 128u + (hkB ^ (((uint32_t)(bA + 1) & 7) * 16u));

    float c0 = 0.0f, c1 = 0.0f, c2 = 0.0f, c3 = 0.0f;
    float hs0 = 0.0f, hs1 = 0.0f, hs2 = 0.0f, hs3 = 0.0f;

    __syncthreads();   // weights + h0 + x0 staged (last full-CTA barrier)

    // ---- cache W fragments for chunks k=64..127 (4 chunks x 4 tiles) ----
    uint32_t wc[4][4][4];
    #pragma unroll
    for (int kc = 0; kc < 4; kc++) {
        const uint32_t off = 65536u + (((uint32_t)(kc * 32) + a2) ^ ax);
        #pragma unroll
        for (int tl = 0; tl < 4; tl++) LDSM4(wc[kc][tl], aw[tl] + off);
    }

    const int barid = 1 + half;

    #pragma unroll 1
    for (int t = 0; t < Ln; t++) {
        const uint32_t bwC   = (t & 1) ? bw1 : bw0;
        unsigned char* anext = smem + ((t & 1) ? SM_ACT0 : SM_ACT1);

        if (t + 1 < Ln) { px0 = xbA[(t + 1) * Dn]; px1 = xbB[(t + 1) * Dn]; }

        // accumulators (f16x2) preloaded with biases:
        // tile0: i/f of jA; tile1: g/o of jA; tile2: i/f of jB; tile3: g/o of jB
        uint32_t ac[8] = {uBIa, uBFa, uBGa, uBOa, uBIb, uBFb, uBGb, uBOb};

        // ---- x-part: chunks 0..3 (k 0..63) ----
        #pragma unroll
        for (int kc = 0; kc < 4; kc++) {
            const uint32_t klo = (uint32_t)(kc * 32);
            uint32_t bf[2];
            LDSM2(bf, bwC + ((klo + bk2) ^ bxm));
            const uint32_t offA = (klo + a2) ^ ax;
            #pragma unroll
            for (int tl = 0; tl < 4; tl++) {
                uint32_t af[4];
                LDSM4(af, aw[tl] + offA);
                MMAH(ac[2 * tl], ac[2 * tl + 1], af, bf[0], bf[1]);
            }
        }
        // ---- h-part cached: chunks 4..7 (k 64..127) ----
        #pragma unroll
        for (int kc = 0; kc < 4; kc++) {
            const uint32_t klo = (uint32_t)(kc * 32);
            uint32_t bf[2];
            LDSM2(bf, bwC + 2048u + ((klo + bk2) ^ bxm));
            #pragma unroll
            for (int tl = 0; tl < 4; tl++)
                MMAH(ac[2 * tl], ac[2 * tl + 1], wc[kc][tl], bf[0], bf[1]);
        }
        // ---- h-part: chunks 8..11 (k 128..191) ----
        #pragma unroll
        for (int kc = 0; kc < 4; kc++) {
            const uint32_t klo = (uint32_t)(kc * 32);
            uint32_t bf[2];
            LDSM2(bf, bwC + 4096u + ((klo + bk2) ^ bxm));
            const uint32_t offA = 131072u + ((klo + a2) ^ ax);
            #pragma unroll
            for (int tl = 0; tl < 4; tl++) {
                uint32_t af[4];
                LDSM4(af, aw[tl] + offA);
                MMAH(ac[2 * tl], ac[2 * tl + 1], af, bf[0], bf[1]);
            }
        }

        // ---- update jA (tiles 0,1) ----
        {
            __half2 si = sig_h2p(u2h(ac[0]));
            __half2 sf = sig_h2p(u2h(ac[1]));
            __half2 tg = tanh_h2(u2h(ac[2]));
            __half2 so = sig_h2p(u2h(ac[3]));
            float2 ig = __half22float2(__hmul2(si, tg));
            float2 ff = __half22float2(sf);
            c0 = fmaf(ff.x, c0, ig.x);
            c1 = fmaf(ff.y, c1, ig.y);
            __half2 hh = __hmul2(so, tanh_h2(__floats2half2_rn(c0, c1)));
            float2 hf = __half22float2(hh);
            hs0 += hf.x; hs1 += hf.y;
            *(__half*)(anext + hoffA0) = __low2half(hh);
            *(__half*)(anext + hoffA1) = __high2half(hh);
        }
        // ---- update jB (tiles 2,3) ----
        {
            __half2 si = sig_h2p(u2h(ac[4]));
            __half2 sf = sig_h2p(u2h(ac[5]));
            __half2 tg = tanh_h2(u2h(ac[6]));
            __half2 so = sig_h2p(u2h(ac[7]));
            float2 ig = __half22float2(__hmul2(si, tg));
            float2 ff = __half22float2(sf);
            c2 = fmaf(ff.x, c2, ig.x);
            c3 = fmaf(ff.y, c3, ig.y);
            __half2 hh = __hmul2(so, tanh_h2(__floats2half2_rn(c2, c3)));
            float2 hf = __half22float2(hh);
            hs2 += hf.x; hs3 += hf.y;
            *(__half*)(anext + hoffB0) = __low2half(hh);
            *(__half*)(anext + hoffB1) = __high2half(hh);
        }

        // stage x_{t+1}
        if (t + 1 < Ln) {
            *(__half*)(anext + xo0) = __float2half(px0);
            *(__half*)(anext + xo1) = __float2half(px1);
        }
        // half-scoped barrier: only this half's 256 threads converge
        asm volatile("bar.sync %0, %1;" :: "r"(barid), "r"(256) : "memory");
    }

    g_rep[(size_t)(b0 + bA)     * Hn + jA] = hs0;
    g_rep[(size_t)(b0 + bA + 1) * Hn + jA] = hs1;
    g_rep[(size_t)(b0 + bA)     * Hn + jB] = hs2;
    g_rep[(size_t)(b0 + bA + 1) * Hn + jB] = hs3;
}

// ---------------- head: mean over cycles + classifier + log_softmax ----------------
extern "C" __global__ void head_kernel(const float* __restrict__ Wcls,  // [10][128]
                                       const float* __restrict__ bcls,  // [10]
                                       float* __restrict__ out)         // [64][10]
{
    __shared__ float gm[Hn];
    __shared__ float lg[NCLSn];
    const int g = blockIdx.x, tid = threadIdx.x;

    float s = 0.0f;
    for (int cc = 0; cc < Cn; cc++)
        s += g_rep[(size_t)(g * Cn + cc) * Hn + tid];
    gm[tid] = s * (1.0f / (float)Cn);
    __syncthreads();

    if (tid < NCLSn) {
        float a = bcls[tid];
        #pragma unroll 4
        for (int k = 0; k < Hn; k++) a += gm[k] * Wcls[tid * Hn + k];
        lg[tid] = a;
    }
    __syncthreads();

    if (tid == 0) {
        float m = lg[0];
        for (int i = 1; i < NCLSn; i++) m = fmaxf(m, lg[i]);
        float se = 0.0f;
        for (int i = 0; i < NCLSn; i++) se += expf(lg[i] - m);
        float lse = m + logf(se);
        for (int i = 0; i < NCLSn; i++) out[g * NCLSn + i] = lg[i] - lse;
    }
}

extern "C" void kernel_launch(void* const* d_in, const int* in_sizes, int n_in,
                              void* d_out, int out_size)
{
    const float* x    = (const float*)d_in[0];
    const float* Wih  = (const float*)d_in[1];
    const float* Whh  = (const float*)d_in[2];
    const float* bih  = (const float*)d_in[3];
    const float* bhh  = (const float*)d_in[4];
    const float* Wcls = (const float*)d_in[5];
    const float* bcls = (const float*)d_in[6];
    float* out = (float*)d_out;

    cudaFuncSetAttribute(lstm_kernel,
                         cudaFuncAttributeMaxDynamicSharedMemorySize, SM_TOTAL);

    lstm_kernel<<<NCTA, NTHR, SM_TOTAL>>>(x, Wih, Whh, bih, bhh);
    head_kernel<<<Gn, Hn>>>(Wcls, bcls, out);
}